// round 17
// baseline (speedup 1.0000x reference)
#include <cuda_runtime.h>
#include <cuda_fp16.h>
#include <cstdint>

#define MROWS  4096   // B*T
#define DMODEL 1024
#define T_SEQ  2048
#define NB     2
#define NH     16
#define DH     64
#define QSCALE 0.1803368801111244f   // 0.125 * log2(e)

// ---------------- scratch (__device__ globals: allocation-free rule) --------
__device__ __half g_Q [MROWS * DMODEL];                          // Q single (pre-scaled)
__device__ __half g_K [MROWS * DMODEL];                          // K single fp16
__device__ __half g_V [MROWS * DMODEL];                          // V single fp16
__device__ __half g_x [MROWS * DMODEL];                          // x single fp16
__device__ __half g_Z [MROWS * DMODEL];                          // Z single fp16
__device__ __half g_W[4][DMODEL * DMODEL];                       // transposed [N,K]

// ---------------------------------------------------------------------------
// PTX helpers (plain sm_103: cp.async, ldmatrix, mma.sync, ex2.approx)
// ---------------------------------------------------------------------------
__device__ __forceinline__ uint32_t smem_u32(const void* p) {
    uint32_t a;
    asm("{ .reg .u64 t; cvta.to.shared.u64 t, %1; cvt.u32.u64 %0, t; }"
        : "=r"(a) : "l"(p));
    return a;
}
__device__ __forceinline__ void cp_async16(uint32_t dst, const void* src) {
    asm volatile("cp.async.cg.shared.global [%0], [%1], 16;" :: "r"(dst), "l"(src));
}
#define CP_COMMIT() asm volatile("cp.async.commit_group;" ::: "memory")
#define CP_WAIT(n)  asm volatile("cp.async.wait_group %0;" :: "n"(n) : "memory")
#define SW128(off)  ((off) ^ (((off) >> 3) & 0x70))

__device__ __forceinline__ void ldsm_x4(uint32_t* r, uint32_t addr) {
    asm volatile("ldmatrix.sync.aligned.m8n8.x4.shared.b16 {%0,%1,%2,%3}, [%4];"
                 : "=r"(r[0]), "=r"(r[1]), "=r"(r[2]), "=r"(r[3]) : "r"(addr));
}
__device__ __forceinline__ void ldsm_x4_t(uint32_t* r, uint32_t addr) {
    asm volatile("ldmatrix.sync.aligned.m8n8.x4.trans.shared.b16 {%0,%1,%2,%3}, [%4];"
                 : "=r"(r[0]), "=r"(r[1]), "=r"(r[2]), "=r"(r[3]) : "r"(addr));
}
__device__ __forceinline__ void mma_f16(float* c, const uint32_t* a,
                                        uint32_t b0, uint32_t b1) {
    asm volatile(
        "mma.sync.aligned.m16n8k16.row.col.f32.f16.f16.f32 "
        "{%0,%1,%2,%3}, {%4,%5,%6,%7}, {%8,%9}, {%0,%1,%2,%3};"
        : "+f"(c[0]), "+f"(c[1]), "+f"(c[2]), "+f"(c[3])
        : "r"(a[0]), "r"(a[1]), "r"(a[2]), "r"(a[3]), "r"(b0), "r"(b1));
}
__device__ __forceinline__ float ex2(float x) {
    float r; asm("ex2.approx.f32 %0, %1;" : "=f"(r) : "f"(x)); return r;
}
__device__ __forceinline__ uint32_t pack_h2(float v0, float v1) {
    __half2 h = __floats2half2_rn(v0, v1);
    return *(uint32_t*)&h;
}

// ---------------------------------------------------------------------------
// Conversion kernels
// ---------------------------------------------------------------------------
__global__ __launch_bounds__(256) void cvt_x(const float* __restrict__ src,
                                             __half* __restrict__ dst, int n4)
{
    int i = blockIdx.x * 256 + threadIdx.x;
    if (i >= n4) return;
    float4 v = ((const float4*)src)[i];
    ((uint2*)dst)[i] = make_uint2(pack_h2(v.x, v.y), pack_h2(v.z, v.w));
}

// All 4 weights in one launch: W[K,N] fp32 -> transposed fp16 [N,K]
__global__ __launch_bounds__(256) void split_wt_h4(
    const float* __restrict__ W0, const float* __restrict__ W1,
    const float* __restrict__ W2, const float* __restrict__ W3,
    __half* __restrict__ T)
{
    __shared__ float tile[32][33];
    const float* Ws[4] = {W0, W1, W2, W3};
    const float* W = Ws[blockIdx.z];
    __half* Tz = T + (size_t)blockIdx.z * DMODEL * DMODEL;
    const int tx = threadIdx.x, ty = threadIdx.y;        // (32, 8)
    const int bn = blockIdx.x * 32, bk = blockIdx.y * 32;
#pragma unroll
    for (int j = 0; j < 32; j += 8)
        tile[ty + j][tx] = W[(size_t)(bk + ty + j) * DMODEL + bn + tx];
    __syncthreads();
#pragma unroll
    for (int j = 0; j < 32; j += 8)
        Tz[(size_t)(bn + ty + j) * DMODEL + bk + tx] = __float2half_rn(tile[tx][ty + j]);
}

// ---------------------------------------------------------------------------
// fp16 mma.sync GEMM body: C = A[M,K] * B[N,K]^T.
// CTA 128x128, BK=64, 512 threads = 16 warps (4m x 4n -> warp 32x32),
// 3-stage cp.async ring. 32 warps/SM (2 CTA) = 8/SMSP for latency hiding.
// ---------------------------------------------------------------------------
#define G_TILE   16384u                    // 128 rows x 128B
#define G_STAGE  (2 * G_TILE)              // A, B
#define G_NST    (DMODEL / 64)             // 16

extern __shared__ char dyn_smem[];

__device__ __forceinline__ void gemm_body(
    const __half* __restrict__ A, const __half* __restrict__ B,
    float* __restrict__ Cf, __half* __restrict__ Ch, float scale)
{
    const uint32_t sb = smem_u32(dyn_smem);
    const int tid  = threadIdx.x;
    const int lane = tid & 31;
    const int wid  = tid >> 5;            // 0..15
    const int m0   = (wid & 3) * 32;
    const int n0   = (wid >> 2) * 32;
    const int row0 = blockIdx.y * 128;
    const int col0 = blockIdx.x * 128;

    const __half* srcs[2] = {A, B};

    float acc[2][4][4];
#pragma unroll
    for (int a = 0; a < 2; a++)
#pragma unroll
        for (int b = 0; b < 4; b++)
#pragma unroll
            for (int d = 0; d < 4; d++) acc[a][b][d] = 0.f;

    const int a_row = lane & 15;
    const int a_col = 8 * (lane >> 4);
    const int b_row = (lane & 7) + 8 * (lane >> 4);
    const int b_col = 8 * ((lane >> 3) & 1);

    auto load_stage = [&](int s) {
        const uint32_t base = sb + (uint32_t)(s % 3) * G_STAGE;
        const int k0 = s * 64;
#pragma unroll
        for (int t = 0; t < 2; t++) {
            const uint32_t tb = base + (uint32_t)t * G_TILE;
            const int gr0 = (t < 1) ? row0 : col0;
            const __half* src = srcs[t];
#pragma unroll
            for (int i = 0; i < 2; i++) {
                int f  = tid + i * 512;        // 0..1023
                int r  = f >> 3;
                int ch = f & 7;
                cp_async16(tb + SW128((uint32_t)(r * 128 + ch * 16)),
                           src + (size_t)(gr0 + r) * DMODEL + k0 + ch * 8);
            }
        }
        CP_COMMIT();
    };

    load_stage(0);
    load_stage(1);

    for (int s = 0; s < G_NST; s++) {
        CP_WAIT(1);
        __syncthreads();
        if (s + 2 < G_NST) load_stage(s + 2);

        const uint32_t base = sb + (uint32_t)(s % 3) * G_STAGE;
        const uint32_t aB = base, bB = base + G_TILE;

#pragma unroll
        for (int kk = 0; kk < 64; kk += 16) {
            uint32_t af[2][4], bf[2][4];
#pragma unroll
            for (int mi = 0; mi < 2; mi++) {
                uint32_t off = SW128((uint32_t)((m0 + mi * 16 + a_row) * 128 +
                                                (kk + a_col) * 2));
                ldsm_x4(af[mi], aB + off);
            }
#pragma unroll
            for (int ng = 0; ng < 2; ng++) {
                uint32_t boff = SW128((uint32_t)((n0 + ng * 16 + b_row) * 128 +
                                                 (kk + b_col) * 2));
                ldsm_x4(bf[ng], bB + boff);
            }
#pragma unroll
            for (int ng = 0; ng < 2; ng++)
#pragma unroll
                for (int mi = 0; mi < 2; mi++) {
                    mma_f16(acc[mi][2 * ng],     af[mi], bf[ng][0], bf[ng][1]);
                    mma_f16(acc[mi][2 * ng + 1], af[mi], bf[ng][2], bf[ng][3]);
                }
        }
    }

#pragma unroll
    for (int mi = 0; mi < 2; mi++) {
        int r = row0 + m0 + mi * 16 + (lane >> 2);
#pragma unroll
        for (int nj = 0; nj < 4; nj++) {
            int c = col0 + n0 + nj * 8 + (lane & 3) * 2;
            float v0 = acc[mi][nj][0] * scale, v1 = acc[mi][nj][1] * scale;
            float v2 = acc[mi][nj][2] * scale, v3 = acc[mi][nj][3] * scale;
            if (Cf) {
                *(float2*)&Cf[(size_t)r * DMODEL + c]       = make_float2(v0, v1);
                *(float2*)&Cf[(size_t)(r + 8) * DMODEL + c] = make_float2(v2, v3);
            } else {
                *(uint32_t*)&Ch[(size_t)r * DMODEL + c]       = pack_h2(v0, v1);
                *(uint32_t*)&Ch[(size_t)(r + 8) * DMODEL + c] = pack_h2(v2, v3);
            }
        }
    }
}

// QKV fused: z = 0,1,2 selects weight + destination (+Q scale)
__global__ __launch_bounds__(512, 2) void gemm_qkv(
    const __half* __restrict__ x, const __half* __restrict__ Wt,
    __half* __restrict__ Q, __half* __restrict__ K, __half* __restrict__ V)
{
    const int z = blockIdx.z;
    __half* outs[3] = {Q, K, V};
    gemm_body(x, Wt + (size_t)z * DMODEL * DMODEL, nullptr, outs[z],
              z == 0 ? QSCALE : 1.0f);
}

__global__ __launch_bounds__(512, 2) void gemm_out(
    const __half* __restrict__ Z, const __half* __restrict__ W,
    float* __restrict__ out)
{
    gemm_body(Z, W, out, nullptr, 1.0f);
}

// ---------------------------------------------------------------------------
// FlashAttention-2 on fp16 mma.sync, causal (unchanged from R14/R15 WIN).
// QK^T 1-term, P.V 1-term. 256 threads (8 warps x m16), Bc=64, double-buffered.
// ---------------------------------------------------------------------------
#define ATT_Q    0u
#define ATT_BUF  16384u          // + (t&1)*16384; K@+0, V@+8192
#define ATT_SMEM 49152u

__global__ __launch_bounds__(256, 2) void attn_tc()
{
    const uint32_t sb = smem_u32(dyn_smem);
    const int tid  = threadIdx.x;
    const int lane = tid & 31;
    const int wid  = tid >> 5;
    const int m0   = wid * 16;
    const int bh   = blockIdx.y;
    const int base = (bh >> 4) * T_SEQ;
    const int h64  = (bh & 15) * DH;
    const int qb   = ((int)gridDim.x - 1 - (int)blockIdx.x) * 128;  // heavy first
    const int ntiles = qb / 64 + 2;

    // ---- load Q tile ----
#pragma unroll
    for (int i = 0; i < 4; i++) {
        int f = tid + 256 * i;
        int r = f >> 3, ch = f & 7;
        uint32_t off = SW128((uint32_t)(r * 128 + ch * 16));
        size_t g = (size_t)(base + qb + r) * DMODEL + h64 + ch * 8;
        cp_async16(sb + ATT_Q + off, &g_Q[g]);
    }
    CP_COMMIT();

    auto load_kv = [&](int t) {
        const uint32_t bufb = sb + ATT_BUF + (uint32_t)(t & 1) * 16384u;
        const int kt = t * 64;
#pragma unroll
        for (int i = 0; i < 2; i++) {
            int f = tid + 256 * i;
            int r = f >> 3, ch = f & 7;
            uint32_t off = SW128((uint32_t)(r * 128 + ch * 16));
            size_t g = (size_t)(base + kt + r) * DMODEL + h64 + ch * 8;
            cp_async16(bufb + off,        &g_K[g]);
            cp_async16(bufb + 8192 + off, &g_V[g]);
        }
        CP_COMMIT();
    };

    load_kv(0);

    const int a_row = lane & 15;
    const int a_col = 8 * (lane >> 4);
    const int b_row = (lane & 7) + 8 * (lane >> 4);
    const int b_col = 8 * ((lane >> 3) & 1);

    // ---- hoist Q fragments into registers ----
    CP_WAIT(1);
    __syncthreads();
    uint32_t qf[4][4];
#pragma unroll
    for (int ks = 0; ks < 4; ks++) {
        uint32_t off = SW128((uint32_t)((m0 + a_row) * 128 + (ks * 16 + a_col) * 2));
        ldsm_x4(qf[ks], sb + ATT_Q + off);
    }

    float o[8][4];
#pragma unroll
    for (int b = 0; b < 8; b++)
#pragma unroll
        for (int d = 0; d < 4; d++) o[b][d] = 0.f;
    float mrow[2] = {-1e30f, -1e30f};
    float lrow[2] = {0.f, 0.f};

    for (int t = 0; t < ntiles; t++) {
        if (t + 1 < ntiles) { load_kv(t + 1); CP_WAIT(1); }
        else                 { CP_WAIT(0); }
        __syncthreads();

        const uint32_t bufb = sb + ATT_BUF + (uint32_t)(t & 1) * 16384u;
        const uint32_t Kb = bufb, Vb = bufb + 8192;
        const int kt = t * 64;

        // ---- S = Q K^T (1-term fp16) ----
        float s[8][4];
#pragma unroll
        for (int b = 0; b < 8; b++)
#pragma unroll
            for (int d = 0; d < 4; d++) s[b][d] = 0.f;

#pragma unroll
        for (int ks = 0; ks < 4; ks++) {
#pragma unroll
            for (int jp = 0; jp < 4; jp++) {
                uint32_t boff = SW128((uint32_t)((jp * 16 + b_row) * 128 +
                                                 (ks * 16 + b_col) * 2));
                uint32_t kh[4];
                ldsm_x4(kh, Kb + boff);
                mma_f16(s[2 * jp],     qf[ks], kh[0], kh[1]);
                mma_f16(s[2 * jp + 1], qf[ks], kh[2], kh[3]);
            }
        }

        // ---- causal mask ----
        if (t >= ntiles - 2) {
            int rlo = qb + m0 + (lane >> 2);
#pragma unroll
            for (int j = 0; j < 8; j++) {
                int c0 = kt + j * 8 + (lane & 3) * 2;
                if (c0 > rlo)         s[j][0] = -1e30f;
                if (c0 + 1 > rlo)     s[j][1] = -1e30f;
                if (c0 > rlo + 8)     s[j][2] = -1e30f;
                if (c0 + 1 > rlo + 8) s[j][3] = -1e30f;
            }
        }

        // ---- online softmax (log2 domain; Q pre-scaled) ----
        {
            float mx0 = -1e30f, mx1 = -1e30f;
#pragma unroll
            for (int j = 0; j < 8; j++) {
                mx0 = fmaxf(mx0, fmaxf(s[j][0], s[j][1]));
                mx1 = fmaxf(mx1, fmaxf(s[j][2], s[j][3]));
            }
            mx0 = fmaxf(mx0, __shfl_xor_sync(0xffffffff, mx0, 1));
            mx0 = fmaxf(mx0, __shfl_xor_sync(0xffffffff, mx0, 2));
            mx1 = fmaxf(mx1, __shfl_xor_sync(0xffffffff, mx1, 1));
            mx1 = fmaxf(mx1, __shfl_xor_sync(0xffffffff, mx1, 2));
            float mn0 = fmaxf(mrow[0], mx0), mn1 = fmaxf(mrow[1], mx1);
            float c0 = ex2(mrow[0] - mn0),   c1 = ex2(mrow[1] - mn1);
            mrow[0] = mn0; mrow[1] = mn1;
            lrow[0] *= c0; lrow[1] *= c1;
#pragma unroll
            for (int j = 0; j < 8; j++) {
                o[j][0] *= c0; o[j][1] *= c0;
                o[j][2] *= c1; o[j][3] *= c1;
            }
            float sum0 = 0.f, sum1 = 0.f;
#pragma unroll
            for (int j = 0; j < 8; j++) {
                float p0 = ex2(s[j][0] - mn0);
                float p1 = ex2(s[j][1] - mn0);
                float p2 = ex2(s[j][2] - mn1);
                float p3 = ex2(s[j][3] - mn1);
                s[j][0] = p0; s[j][1] = p1;
                s[j][2] = p2; s[j][3] = p3;
                sum0 += p0 + p1; sum1 += p2 + p3;
            }
            lrow[0] += sum0; lrow[1] += sum1;
        }

        // ---- O += P V (1-term) ----
#pragma unroll
        for (int ks = 0; ks < 4; ks++) {
            uint32_t ph[4];
            ph[0] = pack_h2(s[2 * ks][0],     s[2 * ks][1]);
            ph[1] = pack_h2(s[2 * ks][2],     s[2 * ks][3]);
            ph[2] = pack_h2(s[2 * ks + 1][0], s[2 * ks + 1][1]);
            ph[3] = pack_h2(s[2 * ks + 1][2], s[2 * ks + 1][3]);
#pragma unroll
            for (int jp = 0; jp < 4; jp++) {
                uint32_t voff = SW128((uint32_t)((ks * 16 + a_row) * 128 +
                                                 (jp * 16 + a_col) * 2));
                uint32_t vh[4];
                ldsm_x4_t(vh, Vb + voff);
                mma_f16(o[2 * jp],     ph, vh[0], vh[1]);
                mma_f16(o[2 * jp + 1], ph, vh[2], vh[3]);
            }
        }
        __syncthreads();
    }

    // ---- finalize: z = O/l, write single fp16 Z ----
    {
        float l0 = lrow[0], l1 = lrow[1];
        l0 += __shfl_xor_sync(0xffffffff, l0, 1);
        l0 += __shfl_xor_sync(0xffffffff, l0, 2);
        l1 += __shfl_xor_sync(0xffffffff, l1, 1);
        l1 += __shfl_xor_sync(0xffffffff, l1, 2);
        float inv0 = 1.f / l0, inv1 = 1.f / l1;
        size_t rlo = (size_t)(base + qb + m0 + (lane >> 2)) * DMODEL;
        size_t rhi = rlo + 8 * DMODEL;
#pragma unroll
        for (int j = 0; j < 8; j++) {
            int c = h64 + j * 8 + (lane & 3) * 2;
            *(uint32_t*)&g_Z[rlo + c] = pack_h2(o[j][0] * inv0, o[j][1] * inv0);
            *(uint32_t*)&g_Z[rhi + c] = pack_h2(o[j][2] * inv1, o[j][3] * inv1);
        }
    }
}

// ---------------------------------------------------------------------------
extern "C" void kernel_launch(void* const* d_in, const int* in_sizes, int n_in,
                              void* d_out, int out_size)
{
    const float* x  = (const float*)d_in[0];
    const float* Wq = (const float*)d_in[1];
    const float* Wk = (const float*)d_in[2];
    const float* Wv = (const float*)d_in[3];
    const float* Wo = (const float*)d_in[4];
    float* out = (float*)d_out;

    __half *Qs, *Ks, *Vs, *xq, *Zq, *Wt;
    cudaGetSymbolAddress((void**)&Qs, g_Q);  cudaGetSymbolAddress((void**)&Ks, g_K);
    cudaGetSymbolAddress((void**)&Vs, g_V);  cudaGetSymbolAddress((void**)&xq, g_x);
    cudaGetSymbolAddress((void**)&Zq, g_Z);  cudaGetSymbolAddress((void**)&Wt, g_W);

    cudaFuncSetAttribute(gemm_qkv, cudaFuncAttributeMaxDynamicSharedMemorySize,
                         3 * G_STAGE);
    cudaFuncSetAttribute(gemm_out, cudaFuncAttributeMaxDynamicSharedMemorySize,
                         3 * G_STAGE);
    cudaFuncSetAttribute(attn_tc, cudaFuncAttributeMaxDynamicSharedMemorySize,
                         ATT_SMEM);

    const size_t WSZ = (size_t)DMODEL * DMODEL;
    const int nx4 = MROWS * DMODEL / 4;

    cvt_x<<<(nx4 + 255) / 256, 256>>>(x, xq, nx4);
    split_wt_h4<<<dim3(DMODEL / 32, DMODEL / 32, 4), dim3(32, 8)>>>(Wq, Wk, Wv, Wo, Wt);

    dim3 ggrid(DMODEL / 128, MROWS / 128, 3);   // (8, 32, 3) — QKV fused
    gemm_qkv<<<ggrid, 512, 3 * G_STAGE>>>(xq, Wt, Qs, Ks, Vs);

    attn_tc<<<dim3(T_SEQ / 128, NB * NH), 256, ATT_SMEM>>>();

    dim3 ogrid(DMODEL / 128, MROWS / 128);      // (8, 32)
    gemm_out<<<ogrid, 512, 3 * G_STAGE>>>(Zq, Wt + 3 * WSZ, out);
}